// round 1
// baseline (speedup 1.0000x reference)
#include <cuda_runtime.h>
#include <math_constants.h>

// Shapes (fixed by the problem):
//   x: [B=32, C=256, H=128, W=128] float32
#define B_  32
#define C_  256
#define HW_ 16384   // 128*128
#define HW4_ 4096   // HW / 4 (float4 groups)
#define XN_BLOCKS 512   // K2 grid: 32 b * 16 blocks/b

// Scratch (device globals — no allocation allowed)
__device__ float g_pooled[B_ * C_];        // 32 KB
__device__ float g_xn[B_ * HW_];           // 2 MB
__device__ float g_ssum[XN_BLOCKS];        // sigmoid partial sums per block
__device__ float g_entro[HW_];             // 64 KB

// ---------------------------------------------------------------------------
// K1: pooled[b,c] = mean over HW of x[b,c,:,:].  One block per (b,c).
// ---------------------------------------------------------------------------
__global__ void __launch_bounds__(256) k_pool(const float* __restrict__ x) {
    const int bc = blockIdx.x;                 // 0 .. 8191
    const float4* __restrict__ p = reinterpret_cast<const float4*>(x) + (size_t)bc * HW4_;

    float s = 0.0f;
#pragma unroll
    for (int i = 0; i < 16; i++) {
        float4 v = p[threadIdx.x + i * 256];
        s += (v.x + v.y) + (v.z + v.w);
    }

    __shared__ float sm[256];
    sm[threadIdx.x] = s;
    __syncthreads();
#pragma unroll
    for (int o = 128; o > 0; o >>= 1) {
        if (threadIdx.x < o) sm[threadIdx.x] += sm[threadIdx.x + o];
        __syncthreads();
    }
    if (threadIdx.x == 0) g_pooled[bc] = sm[0] * (1.0f / (float)HW_);
}

// ---------------------------------------------------------------------------
// K2: xn[b,sp] = (1/C) * sum_c x[b,c,sp] * pooled[b,c]
//     Also accumulates per-block partial sums of sigmoid(xn) (deterministic).
//     One thread per float4 spatial group. 16 blocks per batch image.
// ---------------------------------------------------------------------------
__global__ void __launch_bounds__(256) k_xn(const float* __restrict__ x) {
    const int b   = blockIdx.x >> 4;                       // 0..31
    const int grp = ((blockIdx.x & 15) << 8) + threadIdx.x; // 0..4095

    __shared__ float pw[C_];
    pw[threadIdx.x] = g_pooled[b * C_ + threadIdx.x];
    __syncthreads();

    const float4* __restrict__ xp =
        reinterpret_cast<const float4*>(x) + (size_t)b * C_ * HW4_ + grp;

    float ax = 0.0f, ay = 0.0f, az = 0.0f, aw = 0.0f;
#pragma unroll 8
    for (int c = 0; c < C_; c++) {
        float4 v = xp[(size_t)c * HW4_];
        float w = pw[c];
        ax = fmaf(v.x, w, ax);
        ay = fmaf(v.y, w, ay);
        az = fmaf(v.z, w, az);
        aw = fmaf(v.w, w, aw);
    }
    const float inv = 1.0f / (float)C_;
    float4 xn;
    xn.x = ax * inv; xn.y = ay * inv; xn.z = az * inv; xn.w = aw * inv;
    reinterpret_cast<float4*>(g_xn)[(size_t)b * HW4_ + grp] = xn;

    // sigmoid partials
    float sg = 1.0f / (1.0f + __expf(-xn.x))
             + 1.0f / (1.0f + __expf(-xn.y))
             + 1.0f / (1.0f + __expf(-xn.z))
             + 1.0f / (1.0f + __expf(-xn.w));

    __shared__ float sm[256];
    sm[threadIdx.x] = sg;
    __syncthreads();
#pragma unroll
    for (int o = 128; o > 0; o >>= 1) {
        if (threadIdx.x < o) sm[threadIdx.x] += sm[threadIdx.x + o];
        __syncthreads();
    }
    if (threadIdx.x == 0) g_ssum[blockIdx.x] = sm[0];
}

// ---------------------------------------------------------------------------
// K3: entro[sp] = mean over b of xn[b,sp]
// ---------------------------------------------------------------------------
__global__ void __launch_bounds__(256) k_entro() {
    const int sp = blockIdx.x * 256 + threadIdx.x;
    float a = 0.0f;
#pragma unroll
    for (int b = 0; b < B_; b++) a += g_xn[(size_t)b * HW_ + sp];
    g_entro[sp] = a * (1.0f / (float)B_);
}

// ---------------------------------------------------------------------------
// K4: min/max -> normalize -> 256-bin histogram (last bin right-inclusive)
//     -> entropy / count_nonzero -> combine with sigmoid mean. One block.
// ---------------------------------------------------------------------------
__global__ void __launch_bounds__(256) k_final(float* __restrict__ out) {
    const int tid = threadIdx.x;

    __shared__ float smin[256], smax[256];
    float mn = CUDART_INF_F, mx = -CUDART_INF_F;
    for (int i = tid; i < HW_; i += 256) {
        float v = g_entro[i];
        mn = fminf(mn, v);
        mx = fmaxf(mx, v);
    }
    smin[tid] = mn; smax[tid] = mx;
    __syncthreads();
#pragma unroll
    for (int o = 128; o > 0; o >>= 1) {
        if (tid < o) {
            smin[tid] = fminf(smin[tid], smin[tid + o]);
            smax[tid] = fmaxf(smax[tid], smax[tid + o]);
        }
        __syncthreads();
    }
    const float emin = smin[0];
    const float emax = smax[0];
    const float denom = emax - emin;

    __shared__ int hist[256];
    hist[tid] = 0;
    __syncthreads();

    for (int i = tid; i < HW_; i += 256) {
        // replicate reference: e = (v - emin) / (emax - emin) * 255
        float e = (g_entro[i] - emin) / denom * 255.0f;
        // uniform bins over [0,255], 256 bins, last bin right-inclusive:
        int bin = (int)floorf(e * (256.0f / 255.0f));
        bin = min(max(bin, 0), 255);
        atomicAdd(&hist[bin], 1);
    }
    __syncthreads();

    __shared__ float ssum[256];
    __shared__ int   snz[256];
    float hisv = (float)hist[tid] * (1.0f / (float)HW_);
    ssum[tid] = hisv * (-logf(hisv + 1e-8f));
    snz[tid]  = (hist[tid] != 0) ? 1 : 0;
    __syncthreads();
#pragma unroll
    for (int o = 128; o > 0; o >>= 1) {
        if (tid < o) {
            ssum[tid] += ssum[tid + o];
            snz[tid]  += snz[tid + o];
        }
        __syncthreads();
    }

    if (tid == 0) {
        double ss = 0.0;
        for (int i = 0; i < XN_BLOCKS; i++) ss += (double)g_ssum[i];
        float s = (float)(ss / (double)((size_t)B_ * HW_));
        float entro_final = ssum[0] / (float)snz[0];
        out[0] = s + entro_final * 10.0f;
    }
}

// ---------------------------------------------------------------------------
extern "C" void kernel_launch(void* const* d_in, const int* in_sizes, int n_in,
                              void* d_out, int out_size) {
    const float* x = (const float*)d_in[0];
    float* out = (float*)d_out;

    k_pool<<<B_ * C_, 256>>>(x);
    k_xn<<<XN_BLOCKS, 256>>>(x);
    k_entro<<<HW_ / 256, 256>>>();
    k_final<<<1, 256>>>(out);
}

// round 2
// speedup vs baseline: 1.1493x; 1.1493x over previous
#include <cuda_runtime.h>
#include <math_constants.h>

// Shapes (fixed by the problem):
//   x: [B=32, C=256, H=128, W=128] float32
#define B_  32
#define C_  256
#define HW_ 16384   // 128*128
#define HW4_ 4096   // HW / 4 (float4 groups)
#define XN_BLOCKS 512    // K2 grid: 32 b * 16 blocks/b
#define ENTRO_BLOCKS 64  // K3 grid

// Scratch (device globals — no allocation allowed)
__device__ float g_pooled[B_ * C_];        // 32 KB
__device__ float g_xn[B_ * HW_];           // 2 MB
__device__ float g_ssum[XN_BLOCKS];        // sigmoid partial sums per block
__device__ float g_entro[HW_];             // 64 KB
__device__ float g_mm[ENTRO_BLOCKS * 2];   // per-block (min,max) partials

// ---------------------------------------------------------------------------
// K1: pooled[b,c] = mean over HW of x[b,c,:,:].  One block per (b,c).
// ---------------------------------------------------------------------------
__global__ void __launch_bounds__(256) k_pool(const float* __restrict__ x) {
    const int bc = blockIdx.x;                 // 0 .. 8191
    const float4* __restrict__ p = reinterpret_cast<const float4*>(x) + (size_t)bc * HW4_;

    float s = 0.0f;
#pragma unroll
    for (int i = 0; i < 16; i++) {
        float4 v = p[threadIdx.x + i * 256];
        s += (v.x + v.y) + (v.z + v.w);
    }

    __shared__ float sm[256];
    sm[threadIdx.x] = s;
    __syncthreads();
#pragma unroll
    for (int o = 128; o > 0; o >>= 1) {
        if (threadIdx.x < o) sm[threadIdx.x] += sm[threadIdx.x + o];
        __syncthreads();
    }
    if (threadIdx.x == 0) g_pooled[bc] = sm[0] * (1.0f / (float)HW_);
}

// ---------------------------------------------------------------------------
// K2: xn[b,sp] = (1/C) * sum_c x[b,c,sp] * pooled[b,c]
//     Also accumulates per-block partial sums of sigmoid(xn) (deterministic).
//     One thread per float4 spatial group. 16 blocks per batch image.
// ---------------------------------------------------------------------------
__global__ void __launch_bounds__(256) k_xn(const float* __restrict__ x) {
    const int b   = blockIdx.x >> 4;                        // 0..31
    const int grp = ((blockIdx.x & 15) << 8) + threadIdx.x; // 0..4095

    __shared__ float pw[C_];
    pw[threadIdx.x] = g_pooled[b * C_ + threadIdx.x];
    __syncthreads();

    const float4* __restrict__ xp =
        reinterpret_cast<const float4*>(x) + (size_t)b * C_ * HW4_ + grp;

    float ax = 0.0f, ay = 0.0f, az = 0.0f, aw = 0.0f;
#pragma unroll 8
    for (int c = 0; c < C_; c++) {
        float4 v = xp[(size_t)c * HW4_];
        float w = pw[c];
        ax = fmaf(v.x, w, ax);
        ay = fmaf(v.y, w, ay);
        az = fmaf(v.z, w, az);
        aw = fmaf(v.w, w, aw);
    }
    const float inv = 1.0f / (float)C_;
    float4 xn;
    xn.x = ax * inv; xn.y = ay * inv; xn.z = az * inv; xn.w = aw * inv;
    reinterpret_cast<float4*>(g_xn)[(size_t)b * HW4_ + grp] = xn;

    // sigmoid partials
    float sg = 1.0f / (1.0f + __expf(-xn.x))
             + 1.0f / (1.0f + __expf(-xn.y))
             + 1.0f / (1.0f + __expf(-xn.z))
             + 1.0f / (1.0f + __expf(-xn.w));

    __shared__ float sm[256];
    sm[threadIdx.x] = sg;
    __syncthreads();
#pragma unroll
    for (int o = 128; o > 0; o >>= 1) {
        if (threadIdx.x < o) sm[threadIdx.x] += sm[threadIdx.x + o];
        __syncthreads();
    }
    if (threadIdx.x == 0) g_ssum[blockIdx.x] = sm[0];
}

// ---------------------------------------------------------------------------
// K3: entro[sp] = mean over b of xn[b,sp]; per-block min/max partials.
// ---------------------------------------------------------------------------
__global__ void __launch_bounds__(256) k_entro() {
    const int sp = blockIdx.x * 256 + threadIdx.x;
    float a = 0.0f;
#pragma unroll
    for (int b = 0; b < B_; b++) a += g_xn[(size_t)b * HW_ + sp];
    float v = a * (1.0f / (float)B_);
    g_entro[sp] = v;

    __shared__ float smin[256], smax[256];
    smin[threadIdx.x] = v;
    smax[threadIdx.x] = v;
    __syncthreads();
#pragma unroll
    for (int o = 128; o > 0; o >>= 1) {
        if (threadIdx.x < o) {
            smin[threadIdx.x] = fminf(smin[threadIdx.x], smin[threadIdx.x + o]);
            smax[threadIdx.x] = fmaxf(smax[threadIdx.x], smax[threadIdx.x + o]);
        }
        __syncthreads();
    }
    if (threadIdx.x == 0) {
        g_mm[blockIdx.x * 2 + 0] = smin[0];
        g_mm[blockIdx.x * 2 + 1] = smax[0];
    }
}

// ---------------------------------------------------------------------------
// K4: reduce min/max partials -> histogram (last bin right-inclusive)
//     -> entropy / count_nonzero -> parallel sigmoid-sum reduce -> combine.
//     One block, all reductions tree-parallel (no serial thread-0 loops).
// ---------------------------------------------------------------------------
__global__ void __launch_bounds__(256) k_final(float* __restrict__ out) {
    const int tid = threadIdx.x;

    // --- parallel double reduction of sigmoid partials (deterministic tree)
    __shared__ double sd[256];
    sd[tid] = (double)g_ssum[tid] + (double)g_ssum[tid + 256];
    __syncthreads();
#pragma unroll
    for (int o = 128; o > 0; o >>= 1) {
        if (tid < o) sd[tid] += sd[tid + o];
        __syncthreads();
    }
    // sd[0] now holds total sigmoid sum (read later by tid 0)

    // --- reduce min/max partials (64 pairs)
    __shared__ float smin[64], smax[64];
    if (tid < 64) {
        smin[tid] = g_mm[tid * 2 + 0];
        smax[tid] = g_mm[tid * 2 + 1];
    }
    __syncthreads();
#pragma unroll
    for (int o = 32; o > 0; o >>= 1) {
        if (tid < o) {
            smin[tid] = fminf(smin[tid], smin[tid + o]);
            smax[tid] = fmaxf(smax[tid], smax[tid + o]);
        }
        __syncthreads();
    }
    const float emin = smin[0];
    const float denom = smax[0] - emin;

    // --- histogram (256 uniform bins over [0,255], last bin right-inclusive)
    __shared__ int hist[256];
    hist[tid] = 0;
    __syncthreads();

    for (int i = tid; i < HW_; i += 256) {
        float e = (g_entro[i] - emin) / denom * 255.0f;
        int bin = (int)floorf(e * (256.0f / 255.0f));
        bin = min(max(bin, 0), 255);
        atomicAdd(&hist[bin], 1);
    }
    __syncthreads();

    // --- entropy + nonzero count
    __shared__ float ssum[256];
    __shared__ int   snz[256];
    float hisv = (float)hist[tid] * (1.0f / (float)HW_);
    ssum[tid] = hisv * (-logf(hisv + 1e-8f));
    snz[tid]  = (hist[tid] != 0) ? 1 : 0;
    __syncthreads();
#pragma unroll
    for (int o = 128; o > 0; o >>= 1) {
        if (tid < o) {
            ssum[tid] += ssum[tid + o];
            snz[tid]  += snz[tid + o];
        }
        __syncthreads();
    }

    if (tid == 0) {
        float s = (float)(sd[0] / (double)((size_t)B_ * HW_));
        float entro_final = ssum[0] / (float)snz[0];
        out[0] = s + entro_final * 10.0f;
    }
}

// ---------------------------------------------------------------------------
extern "C" void kernel_launch(void* const* d_in, const int* in_sizes, int n_in,
                              void* d_out, int out_size) {
    const float* x = (const float*)d_in[0];
    float* out = (float*)d_out;

    k_pool<<<B_ * C_, 256>>>(x);
    k_xn<<<XN_BLOCKS, 256>>>(x);
    k_entro<<<ENTRO_BLOCKS, 256>>>();
    k_final<<<1, 256>>>(out);
}

// round 3
// speedup vs baseline: 1.2481x; 1.0860x over previous
#include <cuda_runtime.h>
#include <math_constants.h>

// Shapes (fixed by the problem):
//   x: [B=32, C=256, H=128, W=128] float32
#define B_  32
#define C_  256
#define HW_ 16384   // 128*128
#define HW4_ 4096   // HW / 4 (float4 groups)
#define XN_BLOCKS 512    // K2 grid: 32 b * 16 blocks/b
#define ENTRO_BLOCKS 64  // K3/K4 grid

// Scratch (device globals — no allocation allowed)
__device__ float g_pooled[B_ * C_];        // 32 KB
__device__ float g_xn[B_ * HW_];           // 2 MB
__device__ float g_ssum[XN_BLOCKS];        // sigmoid partial sums per block
__device__ float g_entro[HW_];             // 64 KB
__device__ float g_mm[ENTRO_BLOCKS * 2];   // per-block (min,max) partials
__device__ int   g_hist[256];              // global histogram

// ---------------------------------------------------------------------------
// K1: pooled[b,c] = mean over HW of x[b,c,:,:].  One block per (b,c).
//     Block 0 also zeroes the global histogram for this graph replay.
// ---------------------------------------------------------------------------
__global__ void __launch_bounds__(256) k_pool(const float* __restrict__ x) {
    if (blockIdx.x == 0) g_hist[threadIdx.x] = 0;

    const int bc = blockIdx.x;                 // 0 .. 8191
    const float4* __restrict__ p = reinterpret_cast<const float4*>(x) + (size_t)bc * HW4_;

    float s = 0.0f;
#pragma unroll
    for (int i = 0; i < 16; i++) {
        float4 v = p[threadIdx.x + i * 256];
        s += (v.x + v.y) + (v.z + v.w);
    }

    __shared__ float sm[256];
    sm[threadIdx.x] = s;
    __syncthreads();
#pragma unroll
    for (int o = 128; o > 0; o >>= 1) {
        if (threadIdx.x < o) sm[threadIdx.x] += sm[threadIdx.x + o];
        __syncthreads();
    }
    if (threadIdx.x == 0) g_pooled[bc] = sm[0] * (1.0f / (float)HW_);
}

// ---------------------------------------------------------------------------
// K2: xn[b,sp] = (1/C) * sum_c x[b,c,sp] * pooled[b,c]
//     Also accumulates per-block partial sums of sigmoid(xn) (deterministic).
// ---------------------------------------------------------------------------
__global__ void __launch_bounds__(256) k_xn(const float* __restrict__ x) {
    const int b   = blockIdx.x >> 4;                        // 0..31
    const int grp = ((blockIdx.x & 15) << 8) + threadIdx.x; // 0..4095

    __shared__ float pw[C_];
    pw[threadIdx.x] = g_pooled[b * C_ + threadIdx.x];
    __syncthreads();

    const float4* __restrict__ xp =
        reinterpret_cast<const float4*>(x) + (size_t)b * C_ * HW4_ + grp;

    float ax = 0.0f, ay = 0.0f, az = 0.0f, aw = 0.0f;
#pragma unroll 8
    for (int c = 0; c < C_; c++) {
        float4 v = xp[(size_t)c * HW4_];
        float w = pw[c];
        ax = fmaf(v.x, w, ax);
        ay = fmaf(v.y, w, ay);
        az = fmaf(v.z, w, az);
        aw = fmaf(v.w, w, aw);
    }
    const float inv = 1.0f / (float)C_;
    float4 xn;
    xn.x = ax * inv; xn.y = ay * inv; xn.z = az * inv; xn.w = aw * inv;
    reinterpret_cast<float4*>(g_xn)[(size_t)b * HW4_ + grp] = xn;

    // sigmoid partials
    float sg = 1.0f / (1.0f + __expf(-xn.x))
             + 1.0f / (1.0f + __expf(-xn.y))
             + 1.0f / (1.0f + __expf(-xn.z))
             + 1.0f / (1.0f + __expf(-xn.w));

    __shared__ float sm[256];
    sm[threadIdx.x] = sg;
    __syncthreads();
#pragma unroll
    for (int o = 128; o > 0; o >>= 1) {
        if (threadIdx.x < o) sm[threadIdx.x] += sm[threadIdx.x + o];
        __syncthreads();
    }
    if (threadIdx.x == 0) g_ssum[blockIdx.x] = sm[0];
}

// ---------------------------------------------------------------------------
// K3: entro[sp] = mean over b of xn[b,sp]; per-block min/max partials.
// ---------------------------------------------------------------------------
__global__ void __launch_bounds__(256) k_entro() {
    const int sp = blockIdx.x * 256 + threadIdx.x;
    float a = 0.0f;
#pragma unroll
    for (int b = 0; b < B_; b++) a += g_xn[(size_t)b * HW_ + sp];
    float v = a * (1.0f / (float)B_);
    g_entro[sp] = v;

    __shared__ float smin[256], smax[256];
    smin[threadIdx.x] = v;
    smax[threadIdx.x] = v;
    __syncthreads();
#pragma unroll
    for (int o = 128; o > 0; o >>= 1) {
        if (threadIdx.x < o) {
            smin[threadIdx.x] = fminf(smin[threadIdx.x], smin[threadIdx.x + o]);
            smax[threadIdx.x] = fmaxf(smax[threadIdx.x], smax[threadIdx.x + o]);
        }
        __syncthreads();
    }
    if (threadIdx.x == 0) {
        g_mm[blockIdx.x * 2 + 0] = smin[0];
        g_mm[blockIdx.x * 2 + 1] = smax[0];
    }
}

// ---------------------------------------------------------------------------
// K4: 64 blocks. Each block: reduce the 64 (min,max) partials (redundant,
//     cheap), bin its 256 entro elements into a shared histogram, flush to
//     the global histogram with one atomicAdd per bin.
// ---------------------------------------------------------------------------
__global__ void __launch_bounds__(256) k_hist() {
    const int tid = threadIdx.x;

    __shared__ float smin[64], smax[64];
    __shared__ int hist[256];
    hist[tid] = 0;
    if (tid < 64) {
        smin[tid] = g_mm[tid * 2 + 0];
        smax[tid] = g_mm[tid * 2 + 1];
    }
    __syncthreads();
#pragma unroll
    for (int o = 32; o > 0; o >>= 1) {
        if (tid < o) {
            smin[tid] = fminf(smin[tid], smin[tid + o]);
            smax[tid] = fmaxf(smax[tid], smax[tid + o]);
        }
        __syncthreads();
    }
    const float emin = smin[0];
    const float denom = smax[0] - emin;

    // one element per thread
    float e = (g_entro[blockIdx.x * 256 + tid] - emin) / denom * 255.0f;
    int bin = (int)floorf(e * (256.0f / 255.0f));
    bin = min(max(bin, 0), 255);
    atomicAdd(&hist[bin], 1);
    __syncthreads();

    if (hist[tid] != 0) atomicAdd(&g_hist[tid], hist[tid]);
}

// ---------------------------------------------------------------------------
// K5: entropy over 256 bins + nz, sigmoid-sum reduce (512 partials), output.
// ---------------------------------------------------------------------------
__global__ void __launch_bounds__(256) k_out(float* __restrict__ out) {
    const int tid = threadIdx.x;

    // parallel double reduction of sigmoid partials (deterministic tree)
    __shared__ double sd[256];
    sd[tid] = (double)g_ssum[tid] + (double)g_ssum[tid + 256];
    __syncthreads();
#pragma unroll
    for (int o = 128; o > 0; o >>= 1) {
        if (tid < o) sd[tid] += sd[tid + o];
        __syncthreads();
    }

    // entropy + nonzero count
    __shared__ float ssum[256];
    __shared__ int   snz[256];
    int h = g_hist[tid];
    float hisv = (float)h * (1.0f / (float)HW_);
    ssum[tid] = hisv * (-logf(hisv + 1e-8f));
    snz[tid]  = (h != 0) ? 1 : 0;
    __syncthreads();
#pragma unroll
    for (int o = 128; o > 0; o >>= 1) {
        if (tid < o) {
            ssum[tid] += ssum[tid + o];
            snz[tid]  += snz[tid + o];
        }
        __syncthreads();
    }

    if (tid == 0) {
        float s = (float)(sd[0] / (double)((size_t)B_ * HW_));
        float entro_final = ssum[0] / (float)snz[0];
        out[0] = s + entro_final * 10.0f;
    }
}

// ---------------------------------------------------------------------------
extern "C" void kernel_launch(void* const* d_in, const int* in_sizes, int n_in,
                              void* d_out, int out_size) {
    const float* x = (const float*)d_in[0];
    float* out = (float*)d_out;

    k_pool<<<B_ * C_, 256>>>(x);
    k_xn<<<XN_BLOCKS, 256>>>(x);
    k_entro<<<ENTRO_BLOCKS, 256>>>();
    k_hist<<<ENTRO_BLOCKS, 256>>>();
    k_out<<<1, 256>>>(out);
}